// round 1
// baseline (speedup 1.0000x reference)
#include <cuda_runtime.h>
#include <cstdint>
#include <math.h>

// BaseSmear: project 64^3 grid points into 8 camera images, nearest-neighbor
// gather of 32 feature channels + depth + validity + ray direction.
// Output layout: grid[I=8][37][N=64^3] followed by coordinates[3][N].

#define II 8
#define CC 32
#define HH 240
#define WW 320
#define NN (64*64*64)

__global__ __launch_bounds__(256) void smear_kernel(
    const float* __restrict__ images,   // [8,32,240,320]
    const float* __restrict__ trans,    // [8,3,4]
    const float* __restrict__ Tcw,      // [8,4,4]
    const float* __restrict__ coords,   // [3,64,64,64]
    float* __restrict__ out)            // [8,37,N]
{
    const int bid   = blockIdx.x;
    const int i     = bid >> 10;              // 1024 blocks of 256 threads per image
    const int nbase = (bid & 1023) << 8;
    const int n     = nbase + threadIdx.x;

    const float px = coords[n];
    const float py = coords[NN + n];
    const float pz = coords[2 * NN + n];

    const float* T = Tcw  + i * 16;   // rows of 4x4 world->cam
    const float* P = trans + i * 12;  // rows of 3x4 projection

    // depth = third row of T_cw[:3,:] applied to homogeneous point
    const float depth = T[8] * px + T[9] * py + T[10] * pz + T[11];

    const float w  = P[8] * px + P[9] * py + P[10] * pz + P[11];
    const float ws = (fabsf(w) < 1e-8f) ? 1e-8f : w;
    const float u  = (P[0] * px + P[1] * py + P[2] * pz + P[3]) / ws;
    const float v  = (P[4] * px + P[5] * py + P[6] * pz + P[7]) / ws;

    const bool valid = (u >= 0.0f) && (u <= (float)(WW - 1)) &&
                       (v >= 0.0f) && (v <= (float)(HH - 1)) &&
                       (depth > 0.0f);
    const float validf = valid ? 1.0f : 0.0f;

    // jnp.round == round-half-to-even == rintf (default rounding mode)
    const int ui = (int)fminf(fmaxf(rintf(u), 0.0f), (float)(WW - 1));
    const int vi = (int)fminf(fmaxf(rintf(v), 0.0f), (float)(HH - 1));
    const int poff = vi * WW + ui;

    // camera center = -R^T t ; R[b][a] = T[b*4+a], t[b] = T[b*4+3]
    const float cx = -(T[0] * T[3] + T[4] * T[7] + T[8]  * T[11]);
    const float cy = -(T[1] * T[3] + T[5] * T[7] + T[9]  * T[11]);
    const float cz = -(T[2] * T[3] + T[6] * T[7] + T[10] * T[11]);
    float dx = px - cx, dy = py - cy, dz = pz - cz;
    const float inv = 1.0f / (sqrtf(dx * dx + dy * dy + dz * dz) + 1e-8f);
    dx *= inv; dy *= inv; dz *= inv;

    const float* img = images + (size_t)i * (CC * HH * WW) + poff;
    float* go = out + (size_t)i * 37 * NN + n;

    // 32 independent L2-resident gathers (full unroll -> MLP), coalesced stores
    #pragma unroll
    for (int c = 0; c < CC; c++) {
        go[(size_t)c * NN] = __ldg(img + (size_t)c * (HH * WW)) * validf;
    }
    go[(size_t)32 * NN] = depth;
    go[(size_t)33 * NN] = validf;
    go[(size_t)34 * NN] = dx;
    go[(size_t)35 * NN] = dy;
    go[(size_t)36 * NN] = dz;
}

extern "C" void kernel_launch(void* const* d_in, const int* in_sizes, int n_in,
                              void* d_out, int out_size) {
    const float* images = (const float*)d_in[0];
    const float* trans  = (const float*)d_in[1];
    const float* Tcw    = (const float*)d_in[2];
    const float* coords = (const float*)d_in[3];
    float* out = (float*)d_out;

    smear_kernel<<<II * (NN / 256), 256>>>(images, trans, Tcw, coords, out);

    // Second output: coordinates passthrough, appended after the grid.
    cudaMemcpyAsync(out + (size_t)II * 37 * NN, coords,
                    (size_t)3 * NN * sizeof(float),
                    cudaMemcpyDeviceToDevice, 0);
}

// round 2
// speedup vs baseline: 1.2907x; 1.2907x over previous
#include <cuda_runtime.h>
#include <cstdint>
#include <math.h>

// BaseSmear: project 64^3 grid points into 8 camera images, nearest-neighbor
// gather of 32 feature channels + depth + validity + ray direction.
//
// Two-phase plan:
//   1) transpose images [I,C,H,W] -> [I,H,W,C] (channels-last) into __device__
//      scratch. Makes the per-point 32-channel gather 4 sectors instead of 32.
//   2) main kernel: project, gather 8x float4 (128B aligned), coalesced stores.

#define II 8
#define CC 32
#define HH 240
#define WW 320
#define HW (HH*WW)          // 76800
#define NN (64*64*64)

__device__ float g_imgT[(size_t)II * HW * CC];   // 78.6 MB channels-last scratch

// ---- Phase 1: [C, HW] -> [HW, C] tile transpose per image ------------------
__global__ __launch_bounds__(256) void transpose_kernel(const float* __restrict__ images) {
    __shared__ float tile[32][33];
    const int tilesPerImg = HW / 32;                 // 2400
    const int i       = blockIdx.x / tilesPerImg;
    const int pixbase = (blockIdx.x % tilesPerImg) * 32;
    const int lane = threadIdx.x & 31;
    const int wy   = threadIdx.x >> 5;               // 0..7

    const float* src = images + (size_t)i * CC * HW + pixbase;
    #pragma unroll
    for (int r = 0; r < 4; r++) {
        const int c = wy + r * 8;
        tile[c][lane] = src[(size_t)c * HW + lane];  // coalesced 128B read per warp
    }
    __syncthreads();
    float* dst = g_imgT + ((size_t)i * HW + pixbase) * CC;
    #pragma unroll
    for (int r = 0; r < 4; r++) {
        const int p = wy + r * 8;
        dst[(size_t)p * CC + lane] = tile[lane][p];  // coalesced 128B write per warp
    }
}

// ---- Phase 2: project + gather + write -------------------------------------
__global__ __launch_bounds__(256) void smear_kernel(
    const float* __restrict__ trans,    // [8,3,4]
    const float* __restrict__ Tcw,      // [8,4,4]
    const float* __restrict__ coords,   // [3,64,64,64]
    float* __restrict__ out)            // [8,37,N]
{
    const int bid   = blockIdx.x;
    const int i     = bid >> 10;              // 1024 blocks of 256 threads per image
    const int n     = ((bid & 1023) << 8) + threadIdx.x;

    const float px = coords[n];
    const float py = coords[NN + n];
    const float pz = coords[2 * NN + n];

    const float* T = Tcw   + i * 16;   // rows of 4x4 world->cam
    const float* P = trans + i * 12;   // rows of 3x4 projection

    const float depth = T[8] * px + T[9] * py + T[10] * pz + T[11];

    const float w  = P[8] * px + P[9] * py + P[10] * pz + P[11];
    const float ws = (fabsf(w) < 1e-8f) ? 1e-8f : w;
    const float u  = (P[0] * px + P[1] * py + P[2] * pz + P[3]) / ws;
    const float v  = (P[4] * px + P[5] * py + P[6] * pz + P[7]) / ws;

    const bool valid = (u >= 0.0f) && (u <= (float)(WW - 1)) &&
                       (v >= 0.0f) && (v <= (float)(HH - 1)) &&
                       (depth > 0.0f);
    const float validf = valid ? 1.0f : 0.0f;

    // jnp.round == round-half-to-even == rintf (default rounding mode)
    const int ui = (int)fminf(fmaxf(rintf(u), 0.0f), (float)(WW - 1));
    const int vi = (int)fminf(fmaxf(rintf(v), 0.0f), (float)(HH - 1));
    const int poff = vi * WW + ui;

    // camera center = -R^T t ; R[b][a] = T[b*4+a], t[b] = T[b*4+3]
    const float cx = -(T[0] * T[3] + T[4] * T[7] + T[8]  * T[11]);
    const float cy = -(T[1] * T[3] + T[5] * T[7] + T[9]  * T[11]);
    const float cz = -(T[2] * T[3] + T[6] * T[7] + T[10] * T[11]);
    float dx = px - cx, dy = py - cy, dz = pz - cz;
    const float inv = 1.0f / (sqrtf(dx * dx + dy * dy + dz * dz) + 1e-8f);
    dx *= inv; dy *= inv; dz *= inv;

    // channels-last gather: 32 floats contiguous, 128B-aligned -> 8x LDG.128
    const float4* img4 = (const float4*)(g_imgT + ((size_t)i * HW + poff) * CC);
    float* go = out + (size_t)i * 37 * NN + n;

    #pragma unroll
    for (int k = 0; k < 8; k++) {
        float4 f = make_float4(0.f, 0.f, 0.f, 0.f);
        if (valid) f = __ldg(img4 + k);          // predicated: no traffic if invalid
        go[(size_t)(4 * k + 0) * NN] = f.x;
        go[(size_t)(4 * k + 1) * NN] = f.y;
        go[(size_t)(4 * k + 2) * NN] = f.z;
        go[(size_t)(4 * k + 3) * NN] = f.w;
    }
    go[(size_t)32 * NN] = depth;
    go[(size_t)33 * NN] = validf;
    go[(size_t)34 * NN] = dx;
    go[(size_t)35 * NN] = dy;
    go[(size_t)36 * NN] = dz;
}

extern "C" void kernel_launch(void* const* d_in, const int* in_sizes, int n_in,
                              void* d_out, int out_size) {
    const float* images = (const float*)d_in[0];
    const float* trans  = (const float*)d_in[1];
    const float* Tcw    = (const float*)d_in[2];
    const float* coords = (const float*)d_in[3];
    float* out = (float*)d_out;

    // coordinates passthrough (independent of the kernels)
    cudaMemcpyAsync(out + (size_t)II * 37 * NN, coords,
                    (size_t)3 * NN * sizeof(float),
                    cudaMemcpyDeviceToDevice, 0);

    transpose_kernel<<<II * (HW / 32), 256>>>(images);
    smear_kernel<<<II * (NN / 256), 256>>>(trans, Tcw, coords, out);
}